// round 7
// baseline (speedup 1.0000x reference)
#include <cuda_runtime.h>
#include <cstdint>

// Q8.8 SiLU via int16 sigmoid LUT.
//   x_q  = clamp(rne(x*256), -32768, 32767)
//   idx  = clamp(x_q, -2048, 2048) + 2048            (exact vs. reference float path)
//   s_q  = table[idx]                                (in [0, 256] -> nonnegative)
//   m    = |x_q| * s_q
//   q    = RNE(m >> 8)  = (m + 127 + ((m>>8)&1)) >> 8
//   out  = sign(x_q) * q / 256.0f
//
// Device-side table dtype is probed at runtime (the harness's type map may have
// widened the int16 JAX array). Probe the 32-bit words at word offsets 1024 and
// 1025 (bytes 4096..4103 — in bounds for every candidate layout):
//   int32  : w0 = table[1024] = 5          (<0x10000), w1 = table[1025] != 0
//   int64  : w0 = lo(table[512]) = 1       (<0x10000), w1 = hi(table[512]) == 0
//   int16  : w0 = 128 | 128<<16 = 0x00800080           (<0x01000000)
//   float32: w0 = bits(5.0f)    = 0x40A00000           (>=0x01000000)

#define THREADS 256
#define TABLE_N 4097

__device__ __forceinline__ void fill_lut(short* tab, const void* table) {
    unsigned w0 = ((const unsigned*)table)[1024];
    unsigned w1 = ((const unsigned*)table)[1025];
    if (w0 < 0x10000u) {
        if (w1 == 0u) {                       // int64 entries
            const long long* t = (const long long*)table;
            for (int i = threadIdx.x; i < TABLE_N; i += THREADS)
                tab[i] = (short)t[i];
        } else {                              // int32 entries
            const int* t = (const int*)table;
            for (int i = threadIdx.x; i < TABLE_N; i += THREADS)
                tab[i] = (short)t[i];
        }
    } else if (w0 < 0x01000000u) {            // genuine int16 entries
        const short* t = (const short*)table;
        for (int i = threadIdx.x; i < TABLE_N; i += THREADS)
            tab[i] = t[i];
    } else {                                  // float32 entries (exact integers)
        const float* t = (const float*)table;
        for (int i = threadIdx.x; i < TABLE_N; i += THREADS)
            tab[i] = (short)__float2int_rn(t[i]);
    }
}

__device__ __forceinline__ float silu_q88(float x, const short* __restrict__ tab) {
    // clamp-then-round == round-then-clamp here: +/-32768.0f, +/-32767.0f exact in fp32
    float f = fminf(fmaxf(x * 256.0f, -32768.0f), 32767.0f);
    int   q = __float2int_rn(f);                 // cvt.rni = round-half-to-even
    int idx = min(max(q, -2048), 2048) + 2048;   // [0, 4096]
    int s   = (int)tab[idx];                     // 0..256
    int sgn = q >> 31;
    int m   = abs(q) * s;                        // nonneg, < 2^31
    int r   = (m + 127 + ((m >> 8) & 1)) >> 8;   // branchless RNE >> 8
    r = (r ^ sgn) - sgn;                         // apply sign
    return (float)r * (1.0f / 256.0f);
}

__global__ void __launch_bounds__(THREADS)
silu_lut_kernel(const float4* __restrict__ x,
                const void*   __restrict__ table,
                float4*       __restrict__ out,
                int n4)
{
    __shared__ short tab[TABLE_N];
    fill_lut(tab, table);
    __syncthreads();

    const int stride = gridDim.x * THREADS;
    for (int i = blockIdx.x * THREADS + threadIdx.x; i < n4; i += stride) {
        float4 v = x[i];
        float4 o;
        o.x = silu_q88(v.x, tab);
        o.y = silu_q88(v.y, tab);
        o.z = silu_q88(v.z, tab);
        o.w = silu_q88(v.w, tab);
        out[i] = o;
    }
}

// Tail handler (n not divisible by 4 — not expected here, but safe).
__global__ void __launch_bounds__(THREADS)
silu_lut_tail(const float* __restrict__ x,
              const void*  __restrict__ table,
              float*       __restrict__ out,
              int start, int n)
{
    __shared__ short tab[TABLE_N];
    fill_lut(tab, table);
    __syncthreads();

    int i = start + blockIdx.x * THREADS + threadIdx.x;
    if (i < n)
        out[i] = silu_q88(x[i], tab);
}

extern "C" void kernel_launch(void* const* d_in, const int* in_sizes, int n_in,
                              void* d_out, int out_size)
{
    // Table = whichever input has the small element count (4097); x = the other.
    int xi = 0, ti = 1;
    if (n_in >= 2 && in_sizes[1] > in_sizes[0]) { xi = 1; ti = 0; }

    const float* x     = (const float*)d_in[xi];
    const void*  table = d_in[ti];
    float*       out   = (float*)d_out;

    int n  = out_size;          // numel(x) == numel(out)
    int n4 = n >> 2;

    // Grid-stride with modest block count: bounds redundant L2 traffic from
    // the per-block shared-LUT fill while still filling every SM ~16 deep.
    int blocks = 2368;
    int work_blocks = (n4 + THREADS - 1) / THREADS;
    if (work_blocks < blocks) blocks = work_blocks;
    if (blocks < 1) blocks = 1;

    if (n4 > 0)
        silu_lut_kernel<<<blocks, THREADS>>>((const float4*)x, table, (float4*)out, n4);

    int tail_start = n4 << 2;
    int tail = n - tail_start;
    if (tail > 0)
        silu_lut_tail<<<(tail + THREADS - 1) / THREADS, THREADS>>>(
            x, table, out, tail_start, n);
}